// round 3
// baseline (speedup 1.0000x reference)
#include <cuda_runtime.h>

// SphericalHarmonics l<=3, e3nn component normalization * 1/sqrt(4pi),
// with input normalization to the unit sphere.
// Pure streaming kernel: 12 B in, 64 B out per edge. HBM-bound.
// Floor ~45-50 us at ~6.5-7 TB/s achieved HBM bandwidth.

// Constants folded with the 'integral' scale K = 1/sqrt(4*pi)
#define K_INV_SQRT_4PI 0.28209479177387814
#define S3   1.7320508075688772
#define S5   2.23606797749979
#define S7   2.6457513110645907
#define S15  3.872983346207417
#define S42_6 1.0801234497346435   // sqrt(42)/6
#define S168_8 1.6201851746019653  // sqrt(168)/8

__global__ __launch_bounds__(256) void sh_l3_kernel(
    const float* __restrict__ x, float* __restrict__ out, int n)
{
    for (int i = blockIdx.x * blockDim.x + threadIdx.x; i < n;
         i += gridDim.x * blockDim.x) {

        // load (coalesced: warp reads 384 contiguous bytes)
        float vx = x[3 * i + 0];
        float vy = x[3 * i + 1];
        float vz = x[3 * i + 2];

        // normalize to unit sphere
        float rinv = rsqrtf(vx * vx + vy * vy + vz * vz);
        vx *= rinv; vy *= rinv; vz *= rinv;

        const float K = (float)K_INV_SQRT_4PI;
        const float s3 = (float)S3;
        const float s5 = (float)S5;
        const float s7 = (float)S7;
        const float s15 = (float)S15;
        const float s42_6 = (float)S42_6;
        const float s168_8 = (float)S168_8;

        float x2 = vx * vx;
        float y2 = vy * vy;
        float z2 = vz * vz;
        float x2z2 = x2 + z2;

        // l = 0
        float sh_0_0 = 1.0f;
        // l = 1
        float sh_1_0 = s3 * vx;
        float sh_1_1 = s3 * vy;
        float sh_1_2 = s3 * vz;
        // l = 2
        float sh_2_0 = s15 * vx * vz;
        float sh_2_1 = s15 * vx * vy;
        float sh_2_2 = s5 * (y2 - 0.5f * x2z2);
        float sh_2_3 = s15 * vy * vz;
        float sh_2_4 = 0.5f * s15 * (z2 - x2);
        // l = 3 (recurrence on l=2 blocks)
        float sh_3_0 = s42_6 * (sh_2_0 * vz + sh_2_4 * vx);
        float sh_3_1 = s7 * sh_2_0 * vy;
        float sh_3_2 = s168_8 * (4.0f * y2 - x2z2) * vx;
        float sh_3_3 = 0.5f * s7 * vy * (2.0f * y2 - 3.0f * x2z2);
        float sh_3_4 = s168_8 * vz * (4.0f * y2 - x2z2);
        float sh_3_5 = s7 * sh_2_4 * vy;
        float sh_3_6 = s42_6 * (sh_2_4 * vz - sh_2_0 * vx);

        // 4x STG.128 — thread writes its own contiguous 64 B; warp covers 2 KB.
        float4* o = (float4*)(out + (size_t)16 * i);
        o[0] = make_float4(K * sh_0_0, K * sh_1_0, K * sh_1_1, K * sh_1_2);
        o[1] = make_float4(K * sh_2_0, K * sh_2_1, K * sh_2_2, K * sh_2_3);
        o[2] = make_float4(K * sh_2_4, K * sh_3_0, K * sh_3_1, K * sh_3_2);
        o[3] = make_float4(K * sh_3_3, K * sh_3_4, K * sh_3_5, K * sh_3_6);
    }
}

extern "C" void kernel_launch(void* const* d_in, const int* in_sizes, int n_in,
                              void* d_out, int out_size) {
    const float* x = (const float*)d_in[0];
    float* out = (float*)d_out;
    int n = in_sizes[0] / 3;  // x is [N, 3] float32
    int threads = 256;
    int blocks = (n + threads - 1) / threads;
    sh_l3_kernel<<<blocks, threads>>>(x, out, n);
}

// round 4
// speedup vs baseline: 1.4160x; 1.4160x over previous
#include <cuda_runtime.h>

// SphericalHarmonics l<=3 (e3nn, 'integral' norm), input normalized to unit sphere.
// R3 showed L1tex-bound (77.6%) from store-wavefront inflation (64 B lane stride).
// This version stages I/O through smem with an XOR-swizzled layout so every
// global access is lane-dense and every smem phase is bank-conflict-free.

#define K_INV_SQRT_4PI 0.28209479177387814
#define S3   1.7320508075688772
#define S5   2.23606797749979
#define S7   2.6457513110645907
#define S15  3.872983346207417
#define S42_6 1.0801234497346435   // sqrt(42)/6
#define S168_8 1.6201851746019653  // sqrt(168)/8

#define NT 256

__global__ __launch_bounds__(NT) void sh_l3_kernel(
    const float* __restrict__ x, float* __restrict__ out, int n)
{
    __shared__ float s_in[NT * 3];          // 3 KB
    __shared__ float4 s_out[NT * 4];        // 16 KB, swizzled

    const int tid = threadIdx.x;
    const int base = blockIdx.x * NT;
    const bool full = (base + NT) <= n;
    const int m = full ? NT : (n - base);   // valid edges in this block

    // ---- phase 1: cooperative vectorized load (dense float4 LDGs) ----
    if (full) {
        const float4* xv = (const float4*)(x + (size_t)base * 3);
        if (tid < (NT * 3) / 4) ((float4*)s_in)[tid] = xv[tid];
    } else {
        for (int j = tid; j < m * 3; j += NT)
            s_in[j] = x[(size_t)base * 3 + j];
    }
    __syncthreads();

    // ---- phase 2: per-thread compute (stride-3 LDS: conflict-free) ----
    float vx = s_in[3 * tid + 0];
    float vy = s_in[3 * tid + 1];
    float vz = s_in[3 * tid + 2];

    float rinv = rsqrtf(vx * vx + vy * vy + vz * vz);
    vx *= rinv; vy *= rinv; vz *= rinv;

    const float K = (float)K_INV_SQRT_4PI;
    const float s3 = (float)S3;
    const float s5 = (float)S5;
    const float s7 = (float)S7;
    const float s15 = (float)S15;
    const float s42_6 = (float)S42_6;
    const float s168_8 = (float)S168_8;

    float x2 = vx * vx;
    float y2 = vy * vy;
    float z2 = vz * vz;
    float x2z2 = x2 + z2;

    float sh_1_0 = s3 * vx;
    float sh_1_1 = s3 * vy;
    float sh_1_2 = s3 * vz;
    float sh_2_0 = s15 * vx * vz;
    float sh_2_1 = s15 * vx * vy;
    float sh_2_2 = s5 * (y2 - 0.5f * x2z2);
    float sh_2_3 = s15 * vy * vz;
    float sh_2_4 = 0.5f * s15 * (z2 - x2);
    float sh_3_0 = s42_6 * (sh_2_0 * vz + sh_2_4 * vx);
    float sh_3_1 = s7 * sh_2_0 * vy;
    float sh_3_2 = s168_8 * (4.0f * y2 - x2z2) * vx;
    float sh_3_3 = 0.5f * s7 * vy * (2.0f * y2 - 3.0f * x2z2);
    float sh_3_4 = s168_8 * vz * (4.0f * y2 - x2z2);
    float sh_3_5 = s7 * sh_2_4 * vy;
    float sh_3_6 = s42_6 * (sh_2_4 * vz - sh_2_0 * vx);

    // Swizzled smem store: quarter q of thread t -> float4 slot t*4 + (q ^ ((t>>1)&3)).
    // For each STS.128 phase (8 lanes), the 4 even-t lanes get distinct swizzle
    // values (t>>1 spans 4 consecutive ints) -> disjoint 4-bank groups; odd-t
    // lanes occupy the other 16-bank half. Conflict-free.
    {
        const int swz = (tid >> 1) & 3;
        float4* so = s_out + tid * 4;
        so[0 ^ swz] = make_float4(K,            K * sh_1_0, K * sh_1_1, K * sh_1_2);
        so[1 ^ swz] = make_float4(K * sh_2_0,   K * sh_2_1, K * sh_2_2, K * sh_2_3);
        so[2 ^ swz] = make_float4(K * sh_2_4,   K * sh_3_0, K * sh_3_1, K * sh_3_2);
        so[3 ^ swz] = make_float4(K * sh_3_3,   K * sh_3_4, K * sh_3_5, K * sh_3_6);
    }
    __syncthreads();

    // ---- phase 3: coalesced write-out (dense STG.128: 4 wavefronts each) ----
    if (full) {
        float4* ov = (float4*)(out + (size_t)base * 16);
        #pragma unroll
        for (int k = 0; k < 4; k++) {
            int f = k * NT + tid;           // output float4 index within block
            int t = f >> 2;
            int q = f & 3;
            // Read phase: lanes 0-3 hit row t0 (even), lanes 4-7 row t0+1 (odd)
            // -> opposite 16-bank halves; q^swz distinct within each. Conflict-free.
            ov[f] = s_out[t * 4 + (q ^ ((t >> 1) & 3))];
        }
    } else {
        for (int j = tid; j < m * 16; j += NT) {
            int t = j >> 4;
            int c = j & 15;
            int q = c >> 2;
            const float* sp = (const float*)&s_out[t * 4 + (q ^ ((t >> 1) & 3))];
            out[(size_t)base * 16 + j] = sp[c & 3];
        }
    }
}

extern "C" void kernel_launch(void* const* d_in, const int* in_sizes, int n_in,
                              void* d_out, int out_size) {
    const float* x = (const float*)d_in[0];
    float* out = (float*)d_out;
    int n = in_sizes[0] / 3;  // x is [N, 3] float32
    int blocks = (n + NT - 1) / NT;
    sh_l3_kernel<<<blocks, NT>>>(x, out, n);
}

// round 6
// speedup vs baseline: 1.4231x; 1.0050x over previous
#include <cuda_runtime.h>

// SphericalHarmonics l<=3 (e3nn, 'integral' norm), input normalized to unit sphere.
// R4: smem-staged dense I/O, block barriers -> 51.5us (DRAM 62%, L1 60%, issue 31%).
// R5: warp-private staging slabs + __syncwarp only. Each warp is an independent
// load->compute->store pipeline; no block-wide rendezvous, so DRAM stays fed.
// K = 1/sqrt(4pi) folded into the SH coefficients (l=3 recurrence inherits K
// linearly from the K-scaled l=2 values).

#define NT 256
#define NWARP (NT / 32)

// K-folded coefficients
#define C_K      0.2820947917738781f   // K
#define C_KS3    0.4886025119029199f   // K*sqrt(3)
#define C_KS5    0.6307831305050401f   // K*sqrt(5)
#define C_KS15   1.0925484305920792f   // K*sqrt(15)
#define C_KS15H  0.5462742152960396f   // K*sqrt(15)/2
#define C_KS5H   0.31539156525252005f  // K*sqrt(5)/2  (for -0.5*x2z2 term folded)
#define C_S7     2.6457513110645907f   // sqrt(7)           (applied to K-scaled sh2)
#define C_S42_6  1.0801234497346435f   // sqrt(42)/6        (applied to K-scaled sh2)
#define C_KS168  0.4570457994644658f   // K*sqrt(168)/8
#define C_KS7H   0.3731763325901154f   // K*sqrt(7)/2

__global__ __launch_bounds__(NT) void sh_l3_kernel(
    const float* __restrict__ x, float* __restrict__ out, int n)
{
    // Warp-private slabs: 96 floats in + 128 float4 out per warp.
    __shared__ float  s_in[NWARP][96];     // 3 KB
    __shared__ float4 s_out[NWARP][128];   // 16 KB

    const int lane = threadIdx.x & 31;
    const int w    = threadIdx.x >> 5;
    const int base = blockIdx.x * NT + w * 32;   // first edge of this warp
    const bool full = (base + 32) <= n;

    if (full) {
        // ---- phase 1: warp loads its own 384 B of input (dense float4) ----
        if (lane < 24) {
            const float4* xv = (const float4*)(x + (size_t)base * 3);
            ((float4*)s_in[w])[lane] = xv[lane];
        }
        __syncwarp();

        // ---- phase 2: compute (stride-3 LDS, gcd(3,32)=1 -> conflict-free) ----
        float vx = s_in[w][3 * lane + 0];
        float vy = s_in[w][3 * lane + 1];
        float vz = s_in[w][3 * lane + 2];

        float rinv = rsqrtf(vx * vx + vy * vy + vz * vz);
        vx *= rinv; vy *= rinv; vz *= rinv;

        float x2 = vx * vx;
        float y2 = vy * vy;
        float z2 = vz * vz;
        float x2z2 = x2 + z2;
        float p4y = 4.0f * y2 - x2z2;

        // l=1 (K folded)
        float o10 = C_KS3 * vx;
        float o11 = C_KS3 * vy;
        float o12 = C_KS3 * vz;
        // l=2 (K folded)
        float o20 = C_KS15 * vx * vz;
        float o21 = C_KS15 * vx * vy;
        float o22 = C_KS5 * y2 - C_KS5H * x2z2;
        float o23 = C_KS15 * vy * vz;
        float o24 = C_KS15H * (z2 - x2);
        // l=3 (recurrence on K-scaled l=2 -> already K-scaled)
        float o30 = C_S42_6 * (o20 * vz + o24 * vx);
        float o31 = C_S7 * o20 * vy;
        float o32 = C_KS168 * p4y * vx;
        float o33 = C_KS7H * vy * (2.0f * y2 - 3.0f * x2z2);
        float o34 = C_KS168 * vz * p4y;
        float o35 = C_S7 * o24 * vy;
        float o36 = C_S42_6 * (o24 * vz - o20 * vx);

        // Swizzled smem store: quarter q of lane t -> slot t*4 + (q ^ ((t>>1)&3)).
        // Conflict-free for both store and read phases (verified bank model).
        {
            const int swz = (lane >> 1) & 3;
            float4* so = s_out[w] + lane * 4;
            so[0 ^ swz] = make_float4(C_K, o10, o11, o12);
            so[1 ^ swz] = make_float4(o20, o21, o22, o23);
            so[2 ^ swz] = make_float4(o24, o30, o31, o32);
            so[3 ^ swz] = make_float4(o33, o34, o35, o36);
        }
        __syncwarp();

        // ---- phase 3: dense write-out (each STG.128 = 512 B contiguous) ----
        float4* ov = (float4*)(out + (size_t)base * 16);
        #pragma unroll
        for (int k = 0; k < 4; k++) {
            int f = k * 32 + lane;
            int t = f >> 2;
            int q = f & 3;
            ov[f] = s_out[w][t * 4 + (q ^ ((t >> 1) & 3))];
        }
    } else {
        // ---- tail fallback (never taken for N = 4M, kept for correctness) ----
        int i = base + lane;
        if (i < n) {
            float vx = x[3 * i + 0];
            float vy = x[3 * i + 1];
            float vz = x[3 * i + 2];
            float rinv = rsqrtf(vx * vx + vy * vy + vz * vz);
            vx *= rinv; vy *= rinv; vz *= rinv;

            float x2 = vx * vx, y2 = vy * vy, z2 = vz * vz;
            float x2z2 = x2 + z2;
            float p4y = 4.0f * y2 - x2z2;

            float o10 = C_KS3 * vx, o11 = C_KS3 * vy, o12 = C_KS3 * vz;
            float o20 = C_KS15 * vx * vz;
            float o21 = C_KS15 * vx * vy;
            float o22 = C_KS5 * y2 - C_KS5H * x2z2;
            float o23 = C_KS15 * vy * vz;
            float o24 = C_KS15H * (z2 - x2);
            float o30 = C_S42_6 * (o20 * vz + o24 * vx);
            float o31 = C_S7 * o20 * vy;
            float o32 = C_KS168 * p4y * vx;
            float o33 = C_KS7H * vy * (2.0f * y2 - 3.0f * x2z2);
            float o34 = C_KS168 * vz * p4y;
            float o35 = C_S7 * o24 * vy;
            float o36 = C_S42_6 * (o24 * vz - o20 * vx);

            float4* o = (float4*)(out + (size_t)16 * i);
            o[0] = make_float4(C_K, o10, o11, o12);
            o[1] = make_float4(o20, o21, o22, o23);
            o[2] = make_float4(o24, o30, o31, o32);
            o[3] = make_float4(o33, o34, o35, o36);
        }
    }
}

extern "C" void kernel_launch(void* const* d_in, const int* in_sizes, int n_in,
                              void* d_out, int out_size) {
    const float* x = (const float*)d_in[0];
    float* out = (float*)d_out;
    int n = in_sizes[0] / 3;  // x is [N, 3] float32
    int blocks = (n + NT - 1) / NT;
    sh_l3_kernel<<<blocks, NT>>>(x, out, n);
}